// round 12
// baseline (speedup 1.0000x reference)
#include <cuda_runtime.h>
#include <stdint.h>

// ============================================================================
// FourierEmbedding via int8 mma.sync m16n8k32 (s8xs8->s32), 2-digit base-128
// fixed-point split: a = S*(i1 + i0/128). Per GEMM: pass1 = i1*j1, pass2 =
// (i1*j0 + i0*j1) sharing one int32 acc (scale 1/128); i0*j0 dropped (~1e-5).
// Scales: features fixed 1/127; weights per-column (precomputed); activations
// per-row (rowmax reduce in epilogue). Dequant to fp32 between passes keeps
// accE accumulation across d exact. R6 barrier skeleton (TM=64, 256 thr,
// 2 CTA/SM, warp grid 2x4, warp tile 32x32). Images: [n][k] s8, hi at byte k,
// lo at 128+k, smem row stride 272 (conflict-free ldmatrix).
// ============================================================================

static constexpr int NROWS   = 131072;
static constexpr int TM      = 64;
static constexpr int THREADS = 256;
static constexpr int RS      = 272;            // smem row stride (bytes)
static constexpr int GIMG    = 128 * 256;      // packed gmem image (32768 B)
static constexpr int SA      = 0;              // A image: 64 rows x RS
static constexpr int SB      = TM * RS;        // 17408
static constexpr int RED2O   = SB + 128 * RS;  // 52224 : float2[4][64]
static constexpr int REDMO   = RED2O + 2048;   // 54272 : float[4][64]
static constexpr int SMEM_BYTES = REDMO + 1024;  // 55296 -> 2 CTA/SM

__device__ __align__(16) unsigned char g_wimg[9 * GIMG];
__device__ float g_tcol[9 * 128];   // per-column weight scale (colmax/127)

// ---------------------------------------------------------------------------
static __device__ __forceinline__ uint32_t smem_u32(const void* p) {
    uint32_t a;
    asm("{ .reg .u64 t; cvta.to.shared.u64 t, %1; cvt.u32.u64 %0, t; }"
        : "=r"(a) : "l"(p));
    return a;
}
static __device__ __forceinline__ void cp_async16(uint32_t dst, const void* src) {
    asm volatile("cp.async.cg.shared.global [%0], [%1], 16;"
                 :: "r"(dst), "l"(src) : "memory");
}
#define CP_COMMIT() asm volatile("cp.async.commit_group;" ::: "memory")
#define CP_WAIT0()  asm volatile("cp.async.wait_group 0;" ::: "memory")
#define BAR_GRP(id) asm volatile("bar.sync %0, 128;" :: "r"(id) : "memory")

static __device__ __forceinline__ void ldsm4(uint32_t (&r)[4], uint32_t addr) {
    asm volatile("ldmatrix.sync.aligned.m8n8.x4.shared.b16 {%0,%1,%2,%3}, [%4];"
        : "=r"(r[0]), "=r"(r[1]), "=r"(r[2]), "=r"(r[3]) : "r"(addr));
}
static __device__ __forceinline__ void mma_s8(int32_t* c, const uint32_t* a,
                                              uint32_t b0, uint32_t b1) {
    asm("mma.sync.aligned.m16n8k32.row.col.s32.s8.s8.s32 "
        "{%0,%1,%2,%3},{%4,%5,%6,%7},{%8,%9},{%0,%1,%2,%3};"
        : "+r"(c[0]), "+r"(c[1]), "+r"(c[2]), "+r"(c[3])
        : "r"(a[0]), "r"(a[1]), "r"(a[2]), "r"(a[3]), "r"(b0), "r"(b1));
}

// quantize two floats already scaled to [-127,127] -> packed hi/lo byte pairs
static __device__ __forceinline__ void quant2(float s0, float s1,
                                              uint32_t& hi2, uint32_t& lo2) {
    const int h0 = __float2int_rn(s0), h1 = __float2int_rn(s1);
    const int l0 = __float2int_rn((s0 - (float)h0) * 128.f);
    const int l1 = __float2int_rn((s1 - (float)h1) * 128.f);
    hi2 = (uint32_t)(h0 & 255) | ((uint32_t)(h1 & 255) << 8);
    lo2 = (uint32_t)(l0 & 255) | ((uint32_t)(l1 & 255) << 8);
}

static __device__ __forceinline__ void dequant_add(
    float (&accf)[2][4][4], const int32_t (&acc)[2][4][4],
    const float* sc, const float2* tt, float f) {
#pragma unroll
    for (int mt = 0; mt < 2; ++mt)
#pragma unroll
        for (int nt = 0; nt < 4; ++nt)
#pragma unroll
            for (int h = 0; h < 2; ++h) {
                const float s = sc[2 * mt + h] * f;
                accf[mt][nt][2 * h]     += s * tt[nt].x * (float)acc[mt][nt][2 * h];
                accf[mt][nt][2 * h + 1] += s * tt[nt].y * (float)acc[mt][nt][2 * h + 1];
            }
}

// K=128 s8 GEMM, 2 passes. Warp tile 32x32: acc[mt][nt][4].
static __device__ __forceinline__ void gemm_s8(uint32_t aB, uint32_t bB,
                                               float (&accf)[2][4][4],
                                               const float* sc, const float2* tt) {
    int32_t acc[2][4][4];
    // ---- pass 1: hi*hi ----
#pragma unroll
    for (int i = 0; i < 2; ++i)
#pragma unroll
        for (int j = 0; j < 4; ++j)
#pragma unroll
            for (int q = 0; q < 4; ++q) acc[i][j][q] = 0;
#pragma unroll
    for (int ks = 0; ks < 4; ++ks) {
        const uint32_t kb = (uint32_t)ks * 32u;
        uint32_t ah[2][4], bh[2][4];
        ldsm4(ah[0], aB + kb);
        ldsm4(ah[1], aB + 16u * RS + kb);
        ldsm4(bh[0], bB + kb);
        ldsm4(bh[1], bB + 16u * RS + kb);
#pragma unroll
        for (int mt = 0; mt < 2; ++mt)
#pragma unroll
            for (int p = 0; p < 2; ++p) {
                mma_s8(acc[mt][2 * p],     ah[mt], bh[p][0], bh[p][1]);
                mma_s8(acc[mt][2 * p + 1], ah[mt], bh[p][2], bh[p][3]);
            }
    }
    dequant_add(accf, acc, sc, tt, 1.0f);
    // ---- pass 2: hi*lo + lo*hi (shared 1/128 scale) ----
#pragma unroll
    for (int i = 0; i < 2; ++i)
#pragma unroll
        for (int j = 0; j < 4; ++j)
#pragma unroll
            for (int q = 0; q < 4; ++q) acc[i][j][q] = 0;
#pragma unroll
    for (int ks = 0; ks < 4; ++ks) {
        const uint32_t kb = (uint32_t)ks * 32u;
        uint32_t ah[2][4], al[2][4], bh[2][4], bl[2][4];
        ldsm4(ah[0], aB + kb);
        ldsm4(ah[1], aB + 16u * RS + kb);
        ldsm4(al[0], aB + kb + 128u);
        ldsm4(al[1], aB + 16u * RS + kb + 128u);
        ldsm4(bh[0], bB + kb);
        ldsm4(bh[1], bB + 16u * RS + kb);
        ldsm4(bl[0], bB + kb + 128u);
        ldsm4(bl[1], bB + 16u * RS + kb + 128u);
#pragma unroll
        for (int mt = 0; mt < 2; ++mt)
#pragma unroll
            for (int p = 0; p < 2; ++p) {
                mma_s8(acc[mt][2 * p],     ah[mt], bl[p][0], bl[p][1]);
                mma_s8(acc[mt][2 * p + 1], ah[mt], bl[p][2], bl[p][3]);
                mma_s8(acc[mt][2 * p],     al[mt], bh[p][0], bh[p][1]);
                mma_s8(acc[mt][2 * p + 1], al[mt], bh[p][2], bh[p][3]);
            }
    }
    dequant_add(accf, acc, sc, tt, 0.0078125f);
}

// ---------------------------------------------------------------------------
// pre-kernel: per-column scales + quantized [n][k] hi/lo images (packed 256B/row)
// ---------------------------------------------------------------------------
__global__ void convert_weights_kernel(const float* __restrict__ w1,
                                       const float* __restrict__ w2,
                                       const float* __restrict__ w3) {
    const int img = blockIdx.x;      // 0..8
    const int tid = threadIdx.x;     // 256
    const float* src;
    if (img < 4)      src = w1 + img * (129 * 128);
    else if (img < 8) src = w2 + (img - 4) * (128 * 128);
    else              src = w3;
    __shared__ float cmax[128];
    if (tid < 128) {
        float mx = 1e-30f;
        for (int k = 0; k < 128; ++k) mx = fmaxf(mx, fabsf(src[k * 128 + tid]));
        cmax[tid] = mx;
        g_tcol[img * 128 + tid] = mx * (1.0f / 127.0f);
    }
    __syncthreads();
    for (int i = tid; i < 8192; i += 256) {
        const int n = i >> 6, p = i & 63;
        const float inv = 127.0f / cmax[n];
        const float v0 = src[(2 * p) * 128 + n] * inv;
        const float v1 = src[(2 * p + 1) * 128 + n] * inv;
        uint32_t hi2, lo2;
        quant2(v0, v1, hi2, lo2);
        unsigned char* dst = g_wimg + (size_t)img * GIMG + n * 256 + 2 * p;
        *reinterpret_cast<uint16_t*>(dst)       = (uint16_t)hi2;
        *reinterpret_cast<uint16_t*>(dst + 128) = (uint16_t)lo2;
    }
}

// ---------------------------------------------------------------------------
__global__ __launch_bounds__(THREADS, 2)
void fe_mma_kernel(const float* __restrict__ cont,   // [N,4]
                   const float* __restrict__ freqs,  // [4,64]
                   const float* __restrict__ w1,     // [4,129,128]
                   const float* __restrict__ b1,     // [4,128]
                   const float* __restrict__ ln1g,   // [4,128]
                   const float* __restrict__ ln1b,   // [4,128]
                   const float* __restrict__ b2,     // [4,128]
                   const float* __restrict__ outg,   // [128]
                   const float* __restrict__ outb,   // [128]
                   const float* __restrict__ b3,     // [128]
                   float* __restrict__ out)          // [N,128]
{
    extern __shared__ unsigned char smem[];
    const uint32_t sbase = smem_u32(smem);
    float2* red2 = reinterpret_cast<float2*>(smem + RED2O);  // [4 wx][64]
    float*  redm = reinterpret_cast<float*>(smem + REDMO);   // [4 wx][64]

    const int tid  = threadIdx.x;
    const int lane = tid & 31;
    const int wid  = tid >> 5;
    const int wy = wid & 1, wx = wid >> 1;
    const int rg = wy * 32, nb = wx * 32;
    const int g = lane >> 2, m = lane & 3;
    const int row0 = blockIdx.x * TM;

    int rr[4];
#pragma unroll
    for (int j = 0; j < 4; ++j) rr[j] = rg + j * 8 + g;

    const uint32_t aBase = sbase + SA
        + (uint32_t)(rg + (lane & 7) + 8 * ((lane >> 3) & 1)) * RS
        + (uint32_t)(lane >> 4) * 16u;
    const uint32_t bBase = sbase + SB
        + (uint32_t)(nb + (lane & 7) + 8 * (lane >> 4)) * RS
        + (uint32_t)((lane >> 3) & 1) * 16u;

    // stage a packed image into SB (16 chunks of 16B per 256B row)
    auto stage = [&](int img) {
        const unsigned char* src = g_wimg + (size_t)img * GIMG;
        for (int i = tid; i < 2048; i += THREADS)
            cp_async16(sbase + SB + (uint32_t)(i >> 4) * RS
                                  + (uint32_t)(i & 15) * 16u,
                       src + i * 16);
        CP_COMMIT();
    };

    const float scFeat[4] = { 1.0f / 127.0f, 1.0f / 127.0f,
                              1.0f / 127.0f, 1.0f / 127.0f };

    float accE[2][4][4];
#pragma unroll
    for (int i = 0; i < 2; ++i)
#pragma unroll
        for (int j = 0; j < 4; ++j)
#pragma unroll
            for (int q = 0; q < 4; ++q) accE[i][j][q] = 0.0f;

    const int frow = tid >> 2;          // featgen: 4 threads per row
    const int fbB  = (tid & 3) * 16;    // 16 freqs -> 16 bytes

#pragma unroll 1
    for (int d = 0; d < 4; ++d) {
        __syncthreads();  // s_A/s_B reuse guard

        stage(d);  // w1[d]
        // featgen -> s_A (cos bytes k[0,64), sin k[64,128), lo at +128)
        {
            const float x = cont[(row0 + frow) * 4 + d];
            uint32_t chi[4], clo[4], shi[4], slo[4];
#pragma unroll
            for (int p = 0; p < 4; ++p) {
                uint32_t h2a, l2a, h2b, l2b;
                float c0, s0, c1, s1, c2, s2, c3, s3;
                const float f0 = freqs[d * 64 + fbB + 4 * p];
                const float f1 = freqs[d * 64 + fbB + 4 * p + 1];
                const float f2 = freqs[d * 64 + fbB + 4 * p + 2];
                const float f3 = freqs[d * 64 + fbB + 4 * p + 3];
                __sincosf(x * f0 * 6.283185307179586477f, &s0, &c0);
                __sincosf(x * f1 * 6.283185307179586477f, &s1, &c1);
                __sincosf(x * f2 * 6.283185307179586477f, &s2, &c2);
                __sincosf(x * f3 * 6.283185307179586477f, &s3, &c3);
                quant2(c0 * 127.f, c1 * 127.f, h2a, l2a);
                quant2(c2 * 127.f, c3 * 127.f, h2b, l2b);
                chi[p] = h2a | (h2b << 16);
                clo[p] = l2a | (l2b << 16);
                quant2(s0 * 127.f, s1 * 127.f, h2a, l2a);
                quant2(s2 * 127.f, s3 * 127.f, h2b, l2b);
                shi[p] = h2a | (h2b << 16);
                slo[p] = l2a | (l2b << 16);
            }
            unsigned char* rowp = smem + SA + frow * RS;
            *reinterpret_cast<uint4*>(rowp + fbB)       = make_uint4(chi[0], chi[1], chi[2], chi[3]);
            *reinterpret_cast<uint4*>(rowp + 64 + fbB)  = make_uint4(shi[0], shi[1], shi[2], shi[3]);
            *reinterpret_cast<uint4*>(rowp + 128 + fbB) = make_uint4(clo[0], clo[1], clo[2], clo[3]);
            *reinterpret_cast<uint4*>(rowp + 192 + fbB) = make_uint4(slo[0], slo[1], slo[2], slo[3]);
        }
        CP_WAIT0();
        __syncthreads();

        // ---- GEMM1 ----
        float acc1[2][4][4];
#pragma unroll
        for (int i = 0; i < 2; ++i)
#pragma unroll
            for (int j = 0; j < 4; ++j)
#pragma unroll
                for (int q = 0; q < 4; ++q) acc1[i][j][q] = 0.0f;
        {
            float2 tt[4];
#pragma unroll
            for (int nt = 0; nt < 4; ++nt)
                tt[nt] = *reinterpret_cast<const float2*>(
                    g_tcol + d * 128 + nb + 8 * nt + 2 * m);
            gemm_s8(aBase, bBase, acc1, scFeat, tt);
        }
        __syncthreads();  // GEMM1 reads done

        stage(4 + d);  // w2[d] (overlaps epilogue)

        // ---- epi1: +x*w1_last +b1, LN, ReLU, rowmax-quant -> s_A ----
        float srq[4];
        {
            const float* w1l = w1 + d * (129 * 128) + 128 * 128;
            const float* b1d = b1 + d * 128;
            float2 wl[4], bb[4];
#pragma unroll
            for (int nt = 0; nt < 4; ++nt) {
                const int c = nb + 8 * nt + 2 * m;
                wl[nt] = *reinterpret_cast<const float2*>(w1l + c);
                bb[nt] = *reinterpret_cast<const float2*>(b1d + c);
            }
            float v[4][4][2];
            float sum[4], sq[4];
#pragma unroll
            for (int j = 0; j < 4; ++j) {
                const float xr = cont[(row0 + rr[j]) * 4 + d];
                float s = 0.f, q = 0.f;
#pragma unroll
                for (int nt = 0; nt < 4; ++nt) {
                    const float v0 = acc1[j >> 1][nt][2 * (j & 1)]     + xr * wl[nt].x + bb[nt].x;
                    const float v1 = acc1[j >> 1][nt][2 * (j & 1) + 1] + xr * wl[nt].y + bb[nt].y;
                    v[j][nt][0] = v0; v[j][nt][1] = v1;
                    s += v0 + v1; q += v0 * v0 + v1 * v1;
                }
                sum[j] = s; sq[j] = q;
            }
#pragma unroll
            for (int msk = 1; msk <= 2; msk <<= 1)
#pragma unroll
                for (int j = 0; j < 4; ++j) {
                    sum[j] += __shfl_xor_sync(0xffffffffu, sum[j], msk);
                    sq[j]  += __shfl_xor_sync(0xffffffffu, sq[j],  msk);
                }
            if (m == 0)
#pragma unroll
                for (int j = 0; j < 4; ++j)
                    red2[wx * 64 + rr[j]] = make_float2(sum[j], sq[j]);
            BAR_GRP(wy + 1);
#pragma unroll
            for (int j = 0; j < 4; ++j)
#pragma unroll
                for (int ox = 0; ox < 4; ++ox)
                    if (ox != wx) {
                        const float2 o = red2[ox * 64 + rr[j]];
                        sum[j] += o.x; sq[j] += o.y;
                    }
            const float* gd = ln1g + d * 128;
            const float* bd = ln1b + d * 128;
            float rmax[4];
#pragma unroll
            for (int j = 0; j < 4; ++j) {
                const float mu = sum[j] * (1.0f / 128.0f);
                const float rs = rsqrtf(sq[j] * (1.0f / 128.0f) - mu * mu + 1e-5f);
                float mx = 0.f;
#pragma unroll
                for (int nt = 0; nt < 4; ++nt) {
                    const int c = nb + 8 * nt + 2 * m;
                    const float2 gg = *reinterpret_cast<const float2*>(gd + c);
                    const float2 ee = *reinterpret_cast<const float2*>(bd + c);
                    const float h0 = fmaxf((v[j][nt][0] - mu) * rs * gg.x + ee.x, 0.f);
                    const float h1 = fmaxf((v[j][nt][1] - mu) * rs * gg.y + ee.y, 0.f);
                    v[j][nt][0] = h0; v[j][nt][1] = h1;
                    mx = fmaxf(mx, fmaxf(h0, h1));
                }
                rmax[j] = mx;
            }
#pragma unroll
            for (int msk = 1; msk <= 2; msk <<= 1)
#pragma unroll
                for (int j = 0; j < 4; ++j)
                    rmax[j] = fmaxf(rmax[j], __shfl_xor_sync(0xffffffffu, rmax[j], msk));
            if (m == 0)
#pragma unroll
                for (int j = 0; j < 4; ++j)
                    redm[wx * 64 + rr[j]] = rmax[j];
            BAR_GRP(wy + 1);
#pragma unroll
            for (int j = 0; j < 4; ++j) {
#pragma unroll
                for (int ox = 0; ox < 4; ++ox)
                    if (ox != wx) rmax[j] = fmaxf(rmax[j], redm[ox * 64 + rr[j]]);
                const float inv = 127.0f / fmaxf(rmax[j], 1e-20f);
                srq[j] = rmax[j] * (1.0f / 127.0f);
                unsigned char* rowp = smem + SA + rr[j] * RS;
#pragma unroll
                for (int nt = 0; nt < 4; ++nt) {
                    const int c = nb + 8 * nt + 2 * m;
                    uint32_t hi2, lo2;
                    quant2(v[j][nt][0] * inv, v[j][nt][1] * inv, hi2, lo2);
                    *reinterpret_cast<uint16_t*>(rowp + c)       = (uint16_t)hi2;
                    *reinterpret_cast<uint16_t*>(rowp + 128 + c) = (uint16_t)lo2;
                }
            }
        }
        CP_WAIT0();
        __syncthreads();

        // ---- GEMM2 -> accE ----
        {
            float2 tt[4];
#pragma unroll
            for (int nt = 0; nt < 4; ++nt)
                tt[nt] = *reinterpret_cast<const float2*>(
                    g_tcol + (4 + d) * 128 + nb + 8 * nt + 2 * m);
            gemm_s8(aBase, bBase, accE, srq, tt);
        }
    }

    __syncthreads();
    stage(8);  // w3
    // ---- epi2: +sum_d b2, LN(outg,outb), ReLU, rowmax-quant -> s_A ----
    float srq[4];
    {
        float v[4][4][2];
        float sum[4], sq[4];
        float2 bs[4];
#pragma unroll
        for (int nt = 0; nt < 4; ++nt) {
            const int c = nb + 8 * nt + 2 * m;
            bs[nt].x = b2[c] + b2[128 + c] + b2[256 + c] + b2[384 + c];
            bs[nt].y = b2[c + 1] + b2[128 + c + 1] + b2[256 + c + 1] + b2[384 + c + 1];
        }
#pragma unroll
        for (int j = 0; j < 4; ++j) {
            float s = 0.f, q = 0.f;
#pragma unroll
            for (int nt = 0; nt < 4; ++nt) {
                const float v0 = accE[j >> 1][nt][2 * (j & 1)]     + bs[nt].x;
                const float v1 = accE[j >> 1][nt][2 * (j & 1) + 1] + bs[nt].y;
                v[j][nt][0] = v0; v[j][nt][1] = v1;
                s += v0 + v1; q += v0 * v0 + v1 * v1;
            }
            sum[j] = s; sq[j] = q;
        }
#pragma unroll
        for (int msk = 1; msk <= 2; msk <<= 1)
#pragma unroll
            for (int j = 0; j < 4; ++j) {
                sum[j] += __shfl_xor_sync(0xffffffffu, sum[j], msk);
                sq[j]  += __shfl_xor_sync(0xffffffffu, sq[j],  msk);
            }
        if (m == 0)
#pragma unroll
            for (int j = 0; j < 4; ++j)
                red2[wx * 64 + rr[j]] = make_float2(sum[j], sq[j]);
        BAR_GRP(wy + 1);
#pragma unroll
        for (int j = 0; j < 4; ++j)
#pragma unroll
            for (int ox = 0; ox < 4; ++ox)
                if (ox != wx) {
                    const float2 o = red2[ox * 64 + rr[j]];
                    sum[j] += o.x; sq[j] += o.y;
                }
        float rmax[4];
#pragma unroll
        for (int j = 0; j < 4; ++j) {
            const float mu = sum[j] * (1.0f / 128.0f);
            const float rs = rsqrtf(sq[j] * (1.0f / 128.0f) - mu * mu + 1e-5f);
            float mx = 0.f;
#pragma unroll
            for (int nt = 0; nt < 4; ++nt) {
                const int c = nb + 8 * nt + 2 * m;
                const float2 gg = *reinterpret_cast<const float2*>(outg + c);
                const float2 ee = *reinterpret_cast<const float2*>(outb + c);
                const float h0 = fmaxf((v[j][nt][0] - mu) * rs * gg.x + ee.x, 0.f);
                const float h1 = fmaxf((v[j][nt][1] - mu) * rs * gg.y + ee.y, 0.f);
                v[j][nt][0] = h0; v[j][nt][1] = h1;
                mx = fmaxf(mx, fmaxf(h0, h1));
            }
            rmax[j] = mx;
        }
#pragma unroll
        for (int msk = 1; msk <= 2; msk <<= 1)
#pragma unroll
            for (int j = 0; j < 4; ++j)
                rmax[j] = fmaxf(rmax[j], __shfl_xor_sync(0xffffffffu, rmax[j], msk));
        if (m == 0)
#pragma unroll
            for (int j = 0; j < 4; ++j)
                redm[wx * 64 + rr[j]] = rmax[j];
        BAR_GRP(wy + 1);
#pragma unroll
        for (int j = 0; j < 4; ++j) {
#pragma unroll
            for (int ox = 0; ox < 4; ++ox)
                if (ox != wx) rmax[j] = fmaxf(rmax[j], redm[ox * 64 + rr[j]]);
            const float inv = 127.0f / fmaxf(rmax[j], 1e-20f);
            srq[j] = rmax[j] * (1.0f / 127.0f);
            unsigned char* rowp = smem + SA + rr[j] * RS;
#pragma unroll
            for (int nt = 0; nt < 4; ++nt) {
                const int c = nb + 8 * nt + 2 * m;
                uint32_t hi2, lo2;
                quant2(v[j][nt][0] * inv, v[j][nt][1] * inv, hi2, lo2);
                *reinterpret_cast<uint16_t*>(rowp + c)       = (uint16_t)hi2;
                *reinterpret_cast<uint16_t*>(rowp + 128 + c) = (uint16_t)lo2;
            }
        }
    }
    CP_WAIT0();
    __syncthreads();

    // ---- GEMM3 + b3 -> out ----
    float acc3[2][4][4];
#pragma unroll
    for (int i = 0; i < 2; ++i)
#pragma unroll
        for (int j = 0; j < 4; ++j)
#pragma unroll
            for (int q = 0; q < 4; ++q) acc3[i][j][q] = 0.0f;
    {
        float2 tt[4];
#pragma unroll
        for (int nt = 0; nt < 4; ++nt)
            tt[nt] = *reinterpret_cast<const float2*>(
                g_tcol + 8 * 128 + nb + 8 * nt + 2 * m);
        gemm_s8(aBase, bBase, acc3, srq, tt);
    }

#pragma unroll
    for (int j = 0; j < 4; ++j) {
        float* orow = out + (size_t)(row0 + rr[j]) * 128;
#pragma unroll
        for (int nt = 0; nt < 4; ++nt) {
            const int c = nb + 8 * nt + 2 * m;
            const float2 bb = *reinterpret_cast<const float2*>(b3 + c);
            *reinterpret_cast<float2*>(orow + c) =
                make_float2(acc3[j >> 1][nt][2 * (j & 1)]     + bb.x,
                            acc3[j >> 1][nt][2 * (j & 1) + 1] + bb.y);
        }
    }
}

// ---------------------------------------------------------------------------
extern "C" void kernel_launch(void* const* d_in, const int* in_sizes, int n_in,
                              void* d_out, int out_size)
{
    const float* cont  = (const float*)d_in[0];
    const float* freqs = (const float*)d_in[1];
    const float* w1    = (const float*)d_in[2];
    const float* b1    = (const float*)d_in[3];
    const float* ln1g  = (const float*)d_in[4];
    const float* ln1b  = (const float*)d_in[5];
    const float* w2    = (const float*)d_in[6];
    const float* b2    = (const float*)d_in[7];
    const float* outg  = (const float*)d_in[8];
    const float* outb  = (const float*)d_in[9];
    const float* w3    = (const float*)d_in[10];
    const float* b3    = (const float*)d_in[11];
    float* out = (float*)d_out;

    convert_weights_kernel<<<9, 256>>>(w1, w2, w3);

    cudaFuncSetAttribute(fe_mma_kernel,
                         cudaFuncAttributeMaxDynamicSharedMemorySize, SMEM_BYTES);
    fe_mma_kernel<<<NROWS / TM, THREADS, SMEM_BYTES>>>(
        cont, freqs, w1, b1, ln1g, ln1b, b2, outg, outb, b3, out);
}

// round 13
// speedup vs baseline: 2.6481x; 2.6481x over previous
#include <cuda_runtime.h>
#include <stdint.h>

// ============================================================================
// FourierEmbedding via warp-level bf16 mma.sync (m16n8k16), 3-term hi/lo split.
// R12 = R6 + (a) half-period (~2.2k cyc) skew for odd CTAs to break the
// observed cross-CTA phase lock, (b) epiA split (bias+reduce before the
// post-GEMM1 barrier, no register carry), (c) fully unrolled ks loop.
// CTA = 64 rows, 256 threads = 8 warps: wy(2 row groups) x wx(4 col groups),
// warp tile 32x32. Weight images pre-built: [n][k] row-major, hi bf16 at k*2,
// lo at 256+k*2, row stride 528 B (conflict-free ldmatrix).
// ============================================================================

static constexpr int NROWS   = 131072;
static constexpr int TM      = 64;
static constexpr int THREADS = 256;
static constexpr int RS      = 528;               // image row stride (bytes)
static constexpr int IMG     = 128 * RS;          // 67584 B per weight image
static constexpr int SA      = 0;                 // A image: 64 rows
static constexpr int SB      = TM * RS;           // 33792
static constexpr int REDO    = SB + IMG;          // 101376
static constexpr int SMEM_BYTES = REDO + 4 * 64 * 8;  // 103424 -> 2 CTA/SM

__device__ __align__(16) unsigned char g_wimg[9 * IMG];

// ---------------------------------------------------------------------------
static __device__ __forceinline__ uint32_t smem_u32(const void* p) {
    uint32_t a;
    asm("{ .reg .u64 t; cvta.to.shared.u64 t, %1; cvt.u32.u64 %0, t; }"
        : "=r"(a) : "l"(p));
    return a;
}
static __device__ __forceinline__ uint32_t cvt_bf16x2(float b, float a) {
    uint32_t r;
    asm("cvt.rn.bf16x2.f32 %0, %1, %2;" : "=r"(r) : "f"(b), "f"(a));
    return r;
}
static __device__ __forceinline__ void pack_hilo(float a, float b,
                                                 uint32_t& hi, uint32_t& lo) {
    hi = cvt_bf16x2(b, a);
    const float ra = a - __uint_as_float(hi << 16);
    const float rb = b - __uint_as_float(hi & 0xffff0000u);
    lo = cvt_bf16x2(rb, ra);
}
static __device__ __forceinline__ void cp_async16(uint32_t dst, const void* src) {
    asm volatile("cp.async.cg.shared.global [%0], [%1], 16;"
                 :: "r"(dst), "l"(src) : "memory");
}
#define CP_COMMIT() asm volatile("cp.async.commit_group;" ::: "memory")
#define CP_WAIT0()  asm volatile("cp.async.wait_group 0;" ::: "memory")

static __device__ __forceinline__ void ldsm4(uint32_t (&r)[4], uint32_t addr) {
    asm volatile("ldmatrix.sync.aligned.m8n8.x4.shared.b16 {%0,%1,%2,%3}, [%4];"
        : "=r"(r[0]), "=r"(r[1]), "=r"(r[2]), "=r"(r[3]) : "r"(addr));
}
static __device__ __forceinline__ void mma16816(float* c, const uint32_t* a,
                                                uint32_t b0, uint32_t b1) {
    asm("mma.sync.aligned.m16n8k16.row.col.f32.bf16.bf16.f32 "
        "{%0,%1,%2,%3},{%4,%5,%6,%7},{%8,%9},{%0,%1,%2,%3};"
        : "+f"(c[0]), "+f"(c[1]), "+f"(c[2]), "+f"(c[3])
        : "r"(a[0]), "r"(a[1]), "r"(a[2]), "r"(a[3]), "r"(b0), "r"(b1));
}

// K=128, 3-term bf16 GEMM. Warp tile 32x32: acc[mt][nt][4], 2 m16 x 4 n8.
static __device__ __forceinline__ void gemm_bf16x3(uint32_t aB, uint32_t bB,
                                                   float (&acc)[2][4][4]) {
#pragma unroll
    for (int ks = 0; ks < 8; ++ks) {
        const uint32_t kb = (uint32_t)ks * 32u;
        uint32_t ah[2][4], al[2][4], bh[2][4], bl[2][4];
        ldsm4(ah[0], aB + kb);
        ldsm4(ah[1], aB + 16u * RS + kb);
        ldsm4(bh[0], bB + kb);
        ldsm4(bh[1], bB + 16u * RS + kb);
        ldsm4(al[0], aB + kb + 256u);
        ldsm4(al[1], aB + 16u * RS + kb + 256u);
#pragma unroll
        for (int mt = 0; mt < 2; ++mt)
#pragma unroll
            for (int p = 0; p < 2; ++p) {
                mma16816(acc[mt][2 * p],     ah[mt], bh[p][0], bh[p][1]);
                mma16816(acc[mt][2 * p + 1], ah[mt], bh[p][2], bh[p][3]);
            }
        ldsm4(bl[0], bB + kb + 256u);
        ldsm4(bl[1], bB + 16u * RS + kb + 256u);
#pragma unroll
        for (int mt = 0; mt < 2; ++mt)
#pragma unroll
            for (int p = 0; p < 2; ++p) {
                mma16816(acc[mt][2 * p],     al[mt], bh[p][0], bh[p][1]);
                mma16816(acc[mt][2 * p + 1], al[mt], bh[p][2], bh[p][3]);
            }
#pragma unroll
        for (int mt = 0; mt < 2; ++mt)
#pragma unroll
            for (int p = 0; p < 2; ++p) {
                mma16816(acc[mt][2 * p],     ah[mt], bl[p][0], bl[p][1]);
                mma16816(acc[mt][2 * p + 1], ah[mt], bl[p][2], bl[p][3]);
            }
    }
}

// ---------------------------------------------------------------------------
// pre-kernel: build 9 weight images (transposed [n][k], hi/lo bf16, stride RS)
// ---------------------------------------------------------------------------
__global__ void convert_weights_kernel(const float* __restrict__ w1,
                                       const float* __restrict__ w2,
                                       const float* __restrict__ w3) {
    const int t = blockIdx.x * blockDim.x + threadIdx.x;  // 9*128*64 = 73728
    const int img = t >> 13;
    const int rem = t & 8191;
    const int n = rem >> 6;
    const int p = rem & 63;          // k-pair
    const float* src;
    if (img < 4)      src = w1 + img * (129 * 128);
    else if (img < 8) src = w2 + (img - 4) * (128 * 128);
    else              src = w3;
    const float v0 = src[(2 * p) * 128 + n];
    const float v1 = src[(2 * p + 1) * 128 + n];
    uint32_t hi, lo;
    pack_hilo(v0, v1, hi, lo);
    unsigned char* dst = g_wimg + img * IMG + n * RS + p * 4;
    *reinterpret_cast<uint32_t*>(dst)       = hi;
    *reinterpret_cast<uint32_t*>(dst + 256) = lo;
}

// ---------------------------------------------------------------------------
__global__ __launch_bounds__(THREADS, 2)
void fe_mma_kernel(const float* __restrict__ cont,   // [N,4]
                   const float* __restrict__ freqs,  // [4,64]
                   const float* __restrict__ w1,     // [4,129,128]
                   const float* __restrict__ b1,     // [4,128]
                   const float* __restrict__ ln1g,   // [4,128]
                   const float* __restrict__ ln1b,   // [4,128]
                   const float* __restrict__ b2,     // [4,128]
                   const float* __restrict__ outg,   // [128]
                   const float* __restrict__ outb,   // [128]
                   const float* __restrict__ b3,     // [128]
                   float* __restrict__ out)          // [N,128]
{
    extern __shared__ unsigned char smem[];
    const uint32_t sbase = smem_u32(smem);
    float2* red = reinterpret_cast<float2*>(smem + REDO);  // [4 wx][64 rows]

    const int tid  = threadIdx.x;
    const int lane = tid & 31;
    const int wid  = tid >> 5;
    const int wy = wid & 1, wx = wid >> 1;
    const int rg = wy * 32, nb = wx * 32;
    const int g = lane >> 2, m = lane & 3;
    const int row0 = blockIdx.x * TM;

    // half-period skew (~2.2k cyc): anti-phase the two co-resident CTAs.
    if (blockIdx.x & 1) {
        float z = 1.0f + (float)tid * 1e-20f;
#pragma unroll 1
        for (int i = 0; i < 550; ++i) z = fmaf(z, 1.0000001f, 1e-30f);
        if (z == 0.0f) red[0] = make_float2(z, z);  // never taken
    }

    int rr[4];
#pragma unroll
    for (int j = 0; j < 4; ++j) rr[j] = rg + j * 8 + g;

    const uint32_t aBase = sbase + SA
        + (uint32_t)(rg + (lane & 7) + 8 * ((lane >> 3) & 1)) * RS
        + (uint32_t)(lane >> 4) * 16u;
    const uint32_t bBase = sbase + SB
        + (uint32_t)(nb + (lane & 7) + 8 * (lane >> 4)) * RS
        + (uint32_t)((lane >> 3) & 1) * 16u;

    float accE[2][4][4];
#pragma unroll
    for (int i = 0; i < 2; ++i)
#pragma unroll
        for (int j = 0; j < 4; ++j)
#pragma unroll
            for (int q = 0; q < 4; ++q) accE[i][j][q] = 0.0f;

    const int frow = tid >> 2;          // featgen: 4 threads per row
    const int fb   = (tid & 3) * 16;    // 16 freqs each

#pragma unroll 1
    for (int d = 0; d < 4; ++d) {
        __syncthreads();  // s_A/s_B reuse guard

        // stage w1[d] image
        {
            const unsigned char* src = g_wimg + d * IMG;
            for (int i = tid; i < IMG / 16; i += THREADS)
                cp_async16(sbase + SB + (uint32_t)i * 16u, src + i * 16);
            CP_COMMIT();
        }
        // featgen -> s_A (cos at k[0,64), sin at k[64,128), lo at +256 B)
        {
            const float x = cont[(row0 + frow) * 4 + d];
            uint32_t chi[8], clo[8], shi[8], slo[8];
#pragma unroll
            for (int p = 0; p < 8; ++p) {
                const float f0 = freqs[d * 64 + fb + 2 * p];
                const float f1 = freqs[d * 64 + fb + 2 * p + 1];
                float c0, s0, c1, s1;
                __sincosf(x * f0 * 6.283185307179586477f, &s0, &c0);
                __sincosf(x * f1 * 6.283185307179586477f, &s1, &c1);
                pack_hilo(c0, c1, chi[p], clo[p]);
                pack_hilo(s0, s1, shi[p], slo[p]);
            }
            unsigned char* rowp = smem + SA + frow * RS;
            *reinterpret_cast<uint4*>(rowp + fb * 2)            = make_uint4(chi[0], chi[1], chi[2], chi[3]);
            *reinterpret_cast<uint4*>(rowp + fb * 2 + 16)       = make_uint4(chi[4], chi[5], chi[6], chi[7]);
            *reinterpret_cast<uint4*>(rowp + 128 + fb * 2)      = make_uint4(shi[0], shi[1], shi[2], shi[3]);
            *reinterpret_cast<uint4*>(rowp + 128 + fb * 2 + 16) = make_uint4(shi[4], shi[5], shi[6], shi[7]);
            *reinterpret_cast<uint4*>(rowp + 256 + fb * 2)      = make_uint4(clo[0], clo[1], clo[2], clo[3]);
            *reinterpret_cast<uint4*>(rowp + 256 + fb * 2 + 16) = make_uint4(clo[4], clo[5], clo[6], clo[7]);
            *reinterpret_cast<uint4*>(rowp + 384 + fb * 2)      = make_uint4(slo[0], slo[1], slo[2], slo[3]);
            *reinterpret_cast<uint4*>(rowp + 384 + fb * 2 + 16) = make_uint4(slo[4], slo[5], slo[6], slo[7]);
        }
        CP_WAIT0();
        __syncthreads();

        // ---- GEMM1 ----
        float acc[2][4][4];
#pragma unroll
        for (int i = 0; i < 2; ++i)
#pragma unroll
            for (int j = 0; j < 4; ++j)
#pragma unroll
                for (int q = 0; q < 4; ++q) acc[i][j][q] = 0.0f;
        gemm_bf16x3(aBase, bBase, acc);

        // ---- epiA (before barrier): bias + raw-x + shfl reduce + red store
        float v[4][4][2];
        float sum[4], sq[4];
        {
            const float* w1l = w1 + d * (129 * 128) + 128 * 128;
            const float* b1d = b1 + d * 128;
            float2 wl[4], bb[4];
#pragma unroll
            for (int nt = 0; nt < 4; ++nt) {
                const int c = nb + 8 * nt + 2 * m;
                wl[nt] = *reinterpret_cast<const float2*>(w1l + c);
                bb[nt] = *reinterpret_cast<const float2*>(b1d + c);
            }
#pragma unroll
            for (int j = 0; j < 4; ++j) {
                const float xr = cont[(row0 + rr[j]) * 4 + d];
                float s = 0.f, q = 0.f;
#pragma unroll
                for (int nt = 0; nt < 4; ++nt) {
                    const float v0 = acc[j >> 1][nt][2 * (j & 1)]     + xr * wl[nt].x + bb[nt].x;
                    const float v1 = acc[j >> 1][nt][2 * (j & 1) + 1] + xr * wl[nt].y + bb[nt].y;
                    v[j][nt][0] = v0; v[j][nt][1] = v1;
                    s += v0 + v1; q += v0 * v0 + v1 * v1;
                }
                sum[j] = s; sq[j] = q;
            }
#pragma unroll
            for (int msk = 1; msk <= 2; msk <<= 1)
#pragma unroll
                for (int j = 0; j < 4; ++j) {
                    sum[j] += __shfl_xor_sync(0xffffffffu, sum[j], msk);
                    sq[j]  += __shfl_xor_sync(0xffffffffu, sq[j],  msk);
                }
            if (m == 0)
#pragma unroll
                for (int j = 0; j < 4; ++j)
                    red[wx * 64 + rr[j]] = make_float2(sum[j], sq[j]);
        }
        __syncthreads();  // GEMM1 reads done CTA-wide; red[] visible

        // stage w2[d] image (overlaps epiB)
        {
            const unsigned char* src = g_wimg + (4 + d) * IMG;
            for (int i = tid; i < IMG / 16; i += THREADS)
                cp_async16(sbase + SB + (uint32_t)i * 16u, src + i * 16);
            CP_COMMIT();
        }
        // ---- epiB: cross-group combine, LN, ReLU -> s_A ----
        {
#pragma unroll
            for (int j = 0; j < 4; ++j)
#pragma unroll
                for (int ox = 0; ox < 4; ++ox)
                    if (ox != wx) {
                        const float2 o = red[ox * 64 + rr[j]];
                        sum[j] += o.x; sq[j] += o.y;
                    }
            const float* gd = ln1g + d * 128;
            const float* bd = ln1b + d * 128;
#pragma unroll
            for (int j = 0; j < 4; ++j) {
                const float mu = sum[j] * (1.0f / 128.0f);
                const float rs = rsqrtf(sq[j] * (1.0f / 128.0f) - mu * mu + 1e-5f);
                unsigned char* rowp = smem + SA + rr[j] * RS;
#pragma unroll
                for (int nt = 0; nt < 4; ++nt) {
                    const int c = nb + 8 * nt + 2 * m;
                    const float2 gg = *reinterpret_cast<const float2*>(gd + c);
                    const float2 ee = *reinterpret_cast<const float2*>(bd + c);
                    const float h0 = fmaxf((v[j][nt][0] - mu) * rs * gg.x + ee.x, 0.f);
                    const float h1 = fmaxf((v[j][nt][1] - mu) * rs * gg.y + ee.y, 0.f);
                    uint32_t hi, lo;
                    pack_hilo(h0, h1, hi, lo);
                    *reinterpret_cast<uint32_t*>(rowp + c * 2)       = hi;
                    *reinterpret_cast<uint32_t*>(rowp + 256 + c * 2) = lo;
                }
            }
        }
        CP_WAIT0();
        __syncthreads();

        // ---- GEMM2 -> accE (accumulated over d) ----
        gemm_bf16x3(aBase, bBase, accE);
    }

    // ---- epi2A (before barrier): + sum_d b2, reduce, red store ----
    float v[4][4][2];
    float sum[4], sq[4];
    {
        float2 bs[4];
#pragma unroll
        for (int nt = 0; nt < 4; ++nt) {
            const int c = nb + 8 * nt + 2 * m;
            bs[nt].x = b2[c] + b2[128 + c] + b2[256 + c] + b2[384 + c];
            bs[nt].y = b2[c + 1] + b2[128 + c + 1] + b2[256 + c + 1] + b2[384 + c + 1];
        }
#pragma unroll
        for (int j = 0; j < 4; ++j) {
            float s = 0.f, q = 0.f;
#pragma unroll
            for (int nt = 0; nt < 4; ++nt) {
                const float v0 = accE[j >> 1][nt][2 * (j & 1)]     + bs[nt].x;
                const float v1 = accE[j >> 1][nt][2 * (j & 1) + 1] + bs[nt].y;
                v[j][nt][0] = v0; v[j][nt][1] = v1;
                s += v0 + v1; q += v0 * v0 + v1 * v1;
            }
            sum[j] = s; sq[j] = q;
        }
#pragma unroll
        for (int msk = 1; msk <= 2; msk <<= 1)
#pragma unroll
            for (int j = 0; j < 4; ++j) {
                sum[j] += __shfl_xor_sync(0xffffffffu, sum[j], msk);
                sq[j]  += __shfl_xor_sync(0xffffffffu, sq[j],  msk);
            }
        if (m == 0)
#pragma unroll
            for (int j = 0; j < 4; ++j)
                red[wx * 64 + rr[j]] = make_float2(sum[j], sq[j]);
    }
    __syncthreads();  // GEMM2 reads done; red visible

    // stage w3 image
    {
        const unsigned char* src = g_wimg + 8 * IMG;
        for (int i = tid; i < IMG / 16; i += THREADS)
            cp_async16(sbase + SB + (uint32_t)i * 16u, src + i * 16);
        CP_COMMIT();
    }
    // ---- epi2B: LN(outg,outb), ReLU -> s_A ----
    {
#pragma unroll
        for (int j = 0; j < 4; ++j)
#pragma unroll
            for (int ox = 0; ox < 4; ++ox)
                if (ox != wx) {
                    const float2 o = red[ox * 64 + rr[j]];
                    sum[j] += o.x; sq[j] += o.y;
                }
#pragma unroll
        for (int j = 0; j < 4; ++j) {
            const float mu = sum[j] * (1.0f / 128.0f);
            const float rs = rsqrtf(sq[j] * (1.0f / 128.0f) - mu * mu + 1e-5f);
            unsigned char* rowp = smem + SA + rr[j] * RS;
#pragma unroll
            for (int nt = 0; nt < 4; ++nt) {
                const int c = nb + 8 * nt + 2 * m;
                const float2 gg = *reinterpret_cast<const float2*>(outg + c);
                const float2 ee = *reinterpret_cast<const float2*>(outb + c);
                const float h0 = fmaxf((v[j][nt][0] - mu) * rs * gg.x + ee.x, 0.f);
                const float h1 = fmaxf((v[j][nt][1] - mu) * rs * gg.y + ee.y, 0.f);
                uint32_t hi, lo;
                pack_hilo(h0, h1, hi, lo);
                *reinterpret_cast<uint32_t*>(rowp + c * 2)       = hi;
                *reinterpret_cast<uint32_t*>(rowp + 256 + c * 2) = lo;
            }
        }
    }
    CP_WAIT0();
    __syncthreads();

    // ---- GEMM3 + b3 -> out ----
    float acc3[2][4][4];
#pragma unroll
    for (int i = 0; i < 2; ++i)
#pragma unroll
        for (int j = 0; j < 4; ++j)
#pragma unroll
            for (int q = 0; q < 4; ++q) acc3[i][j][q] = 0.0f;
    gemm_bf16x3(aBase, bBase, acc3);

#pragma unroll
    for (int j = 0; j < 4; ++j) {
        float* orow = out + (size_t)(row0 + rr[j]) * 128;
#pragma unroll
        for (int nt = 0; nt < 4; ++nt) {
            const int c = nb + 8 * nt + 2 * m;
            const float2 bb = *reinterpret_cast<const float2*>(b3 + c);
            *reinterpret_cast<float2*>(orow + c) =
                make_float2(acc3[j >> 1][nt][2 * (j & 1)]     + bb.x,
                            acc3[j >> 1][nt][2 * (j & 1) + 1] + bb.y);
        }
    }
}

// ---------------------------------------------------------------------------
extern "C" void kernel_launch(void* const* d_in, const int* in_sizes, int n_in,
                              void* d_out, int out_size)
{
    const float* cont  = (const float*)d_in[0];
    const float* freqs = (const float*)d_in[1];
    const float* w1    = (const float*)d_in[2];
    const float* b1    = (const float*)d_in[3];
    const float* ln1g  = (const float*)d_in[4];
    const float* ln1b  = (const float*)d_in[5];
    const float* w2    = (const float*)d_in[6];
    const float* b2    = (const float*)d_in[7];
    const float* outg  = (const float*)d_in[8];
    const float* outb  = (const float*)d_in[9];
    const float* w3    = (const float*)d_in[10];
    const float* b3    = (const float*)d_in[11];
    float* out = (float*)d_out;

    convert_weights_kernel<<<288, 256>>>(w1, w2, w3);

    cudaFuncSetAttribute(fe_mma_kernel,
                         cudaFuncAttributeMaxDynamicSharedMemorySize, SMEM_BYTES);
    fe_mma_kernel<<<NROWS / TM, THREADS, SMEM_BYTES>>>(
        cont, freqs, w1, b1, ln1g, ln1b, b2, outg, outb, b3, out);
}

// round 14
// speedup vs baseline: 2.8299x; 1.0687x over previous
#include <cuda_runtime.h>
#include <stdint.h>

// ============================================================================
// FourierEmbedding via warp-level bf16 mma.sync (m16n8k16), 3-term hi/lo split.
// R13 = exact R6 + FULL unroll of the ks loop (isolated variable; skew and
// epiA-split removed — both shown to regress via register pressure).
// CTA = 64 rows, 256 threads = 8 warps: wy(2 row groups) x wx(4 col groups),
// warp tile 32x32. Weight images pre-built: [n][k] row-major, hi bf16 at k*2,
// lo at 256+k*2, row stride 528 B (conflict-free ldmatrix).
// ============================================================================

static constexpr int NROWS   = 131072;
static constexpr int TM      = 64;
static constexpr int THREADS = 256;
static constexpr int RS      = 528;               // image row stride (bytes)
static constexpr int IMG     = 128 * RS;          // 67584 B per weight image
static constexpr int SA      = 0;                 // A image: 64 rows
static constexpr int SB      = TM * RS;           // 33792
static constexpr int REDO    = SB + IMG;          // 101376
static constexpr int SMEM_BYTES = REDO + 4 * 64 * 8;  // 103424 -> 2 CTA/SM

__device__ __align__(16) unsigned char g_wimg[9 * IMG];

// ---------------------------------------------------------------------------
static __device__ __forceinline__ uint32_t smem_u32(const void* p) {
    uint32_t a;
    asm("{ .reg .u64 t; cvta.to.shared.u64 t, %1; cvt.u32.u64 %0, t; }"
        : "=r"(a) : "l"(p));
    return a;
}
// packs: upper half = bf16(b), lower half = bf16(a)
static __device__ __forceinline__ uint32_t cvt_bf16x2(float b, float a) {
    uint32_t r;
    asm("cvt.rn.bf16x2.f32 %0, %1, %2;" : "=r"(r) : "f"(b), "f"(a));
    return r;
}
static __device__ __forceinline__ void pack_hilo(float a, float b,
                                                 uint32_t& hi, uint32_t& lo) {
    hi = cvt_bf16x2(b, a);
    const float ra = a - __uint_as_float(hi << 16);
    const float rb = b - __uint_as_float(hi & 0xffff0000u);
    lo = cvt_bf16x2(rb, ra);
}
static __device__ __forceinline__ void cp_async16(uint32_t dst, const void* src) {
    asm volatile("cp.async.cg.shared.global [%0], [%1], 16;"
                 :: "r"(dst), "l"(src) : "memory");
}
#define CP_COMMIT() asm volatile("cp.async.commit_group;" ::: "memory")
#define CP_WAIT0()  asm volatile("cp.async.wait_group 0;" ::: "memory")
#define BAR_GRP(id) asm volatile("bar.sync %0, 128;" :: "r"(id) : "memory")

static __device__ __forceinline__ void ldsm4(uint32_t (&r)[4], uint32_t addr) {
    asm volatile("ldmatrix.sync.aligned.m8n8.x4.shared.b16 {%0,%1,%2,%3}, [%4];"
        : "=r"(r[0]), "=r"(r[1]), "=r"(r[2]), "=r"(r[3]) : "r"(addr));
}
static __device__ __forceinline__ void mma16816(float* c, const uint32_t* a,
                                                uint32_t b0, uint32_t b1) {
    asm("mma.sync.aligned.m16n8k16.row.col.f32.bf16.bf16.f32 "
        "{%0,%1,%2,%3},{%4,%5,%6,%7},{%8,%9},{%0,%1,%2,%3};"
        : "+f"(c[0]), "+f"(c[1]), "+f"(c[2]), "+f"(c[3])
        : "r"(a[0]), "r"(a[1]), "r"(a[2]), "r"(a[3]), "r"(b0), "r"(b1));
}

// K=128, 3-term bf16 GEMM. Warp tile 32x32: acc[mt][nt][4], 2 m16 x 4 n8.
// Per ks: ldsm ah/bh/al -> 8x hh -> ldsm bl -> 8x lh -> 8x hl. FULL unroll.
static __device__ __forceinline__ void gemm_bf16x3(uint32_t aB, uint32_t bB,
                                                   float (&acc)[2][4][4]) {
#pragma unroll
    for (int ks = 0; ks < 8; ++ks) {
        const uint32_t kb = (uint32_t)ks * 32u;
        uint32_t ah[2][4], al[2][4], bh[2][4], bl[2][4];
        ldsm4(ah[0], aB + kb);
        ldsm4(ah[1], aB + 16u * RS + kb);
        ldsm4(bh[0], bB + kb);
        ldsm4(bh[1], bB + 16u * RS + kb);
        ldsm4(al[0], aB + kb + 256u);
        ldsm4(al[1], aB + 16u * RS + kb + 256u);
#pragma unroll
        for (int mt = 0; mt < 2; ++mt)
#pragma unroll
            for (int p = 0; p < 2; ++p) {
                mma16816(acc[mt][2 * p],     ah[mt], bh[p][0], bh[p][1]);
                mma16816(acc[mt][2 * p + 1], ah[mt], bh[p][2], bh[p][3]);
            }
        ldsm4(bl[0], bB + kb + 256u);
        ldsm4(bl[1], bB + 16u * RS + kb + 256u);
#pragma unroll
        for (int mt = 0; mt < 2; ++mt)
#pragma unroll
            for (int p = 0; p < 2; ++p) {
                mma16816(acc[mt][2 * p],     al[mt], bh[p][0], bh[p][1]);
                mma16816(acc[mt][2 * p + 1], al[mt], bh[p][2], bh[p][3]);
            }
#pragma unroll
        for (int mt = 0; mt < 2; ++mt)
#pragma unroll
            for (int p = 0; p < 2; ++p) {
                mma16816(acc[mt][2 * p],     ah[mt], bl[p][0], bl[p][1]);
                mma16816(acc[mt][2 * p + 1], ah[mt], bl[p][2], bl[p][3]);
            }
    }
}

// ---------------------------------------------------------------------------
// pre-kernel: build 9 weight images (transposed [n][k], hi/lo bf16, stride RS)
// ---------------------------------------------------------------------------
__global__ void convert_weights_kernel(const float* __restrict__ w1,
                                       const float* __restrict__ w2,
                                       const float* __restrict__ w3) {
    const int t = blockIdx.x * blockDim.x + threadIdx.x;  // 9*128*64 = 73728
    const int img = t >> 13;
    const int rem = t & 8191;
    const int n = rem >> 6;
    const int p = rem & 63;          // k-pair
    const float* src;
    if (img < 4)      src = w1 + img * (129 * 128);
    else if (img < 8) src = w2 + (img - 4) * (128 * 128);
    else              src = w3;
    const float v0 = src[(2 * p) * 128 + n];
    const float v1 = src[(2 * p + 1) * 128 + n];
    uint32_t hi, lo;
    pack_hilo(v0, v1, hi, lo);
    unsigned char* dst = g_wimg + img * IMG + n * RS + p * 4;
    *reinterpret_cast<uint32_t*>(dst)       = hi;
    *reinterpret_cast<uint32_t*>(dst + 256) = lo;
}

// ---------------------------------------------------------------------------
__global__ __launch_bounds__(THREADS, 2)
void fe_mma_kernel(const float* __restrict__ cont,   // [N,4]
                   const float* __restrict__ freqs,  // [4,64]
                   const float* __restrict__ w1,     // [4,129,128]
                   const float* __restrict__ b1,     // [4,128]
                   const float* __restrict__ ln1g,   // [4,128]
                   const float* __restrict__ ln1b,   // [4,128]
                   const float* __restrict__ b2,     // [4,128]
                   const float* __restrict__ outg,   // [128]
                   const float* __restrict__ outb,   // [128]
                   const float* __restrict__ b3,     // [128]
                   float* __restrict__ out)          // [N,128]
{
    extern __shared__ unsigned char smem[];
    const uint32_t sbase = smem_u32(smem);
    float2* red = reinterpret_cast<float2*>(smem + REDO);  // [4 wx][64 rows]

    const int tid  = threadIdx.x;
    const int lane = tid & 31;
    const int wid  = tid >> 5;
    const int wy = wid & 1, wx = wid >> 1;
    const int rg = wy * 32, nb = wx * 32;
    const int g = lane >> 2, m = lane & 3;
    const int row0 = blockIdx.x * TM;

    int rr[4];
#pragma unroll
    for (int j = 0; j < 4; ++j) rr[j] = rg + j * 8 + g;

    const uint32_t aBase = sbase + SA
        + (uint32_t)(rg + (lane & 7) + 8 * ((lane >> 3) & 1)) * RS
        + (uint32_t)(lane >> 4) * 16u;
    const uint32_t bBase = sbase + SB
        + (uint32_t)(nb + (lane & 7) + 8 * (lane >> 4)) * RS
        + (uint32_t)((lane >> 3) & 1) * 16u;

    float accE[2][4][4];
#pragma unroll
    for (int i = 0; i < 2; ++i)
#pragma unroll
        for (int j = 0; j < 4; ++j)
#pragma unroll
            for (int q = 0; q < 4; ++q) accE[i][j][q] = 0.0f;

    const int frow = tid >> 2;          // featgen: 4 threads per row
    const int fb   = (tid & 3) * 16;    // 16 freqs each

#pragma unroll 1
    for (int d = 0; d < 4; ++d) {
        __syncthreads();  // s_A/s_B reuse guard

        // stage w1[d] image
        {
            const unsigned char* src = g_wimg + d * IMG;
            for (int i = tid; i < IMG / 16; i += THREADS)
                cp_async16(sbase + SB + (uint32_t)i * 16u, src + i * 16);
            CP_COMMIT();
        }
        // featgen -> s_A (cos at k[0,64), sin at k[64,128), lo at +256 B)
        {
            const float x = cont[(row0 + frow) * 4 + d];
            uint32_t chi[8], clo[8], shi[8], slo[8];
#pragma unroll
            for (int p = 0; p < 8; ++p) {
                const float f0 = freqs[d * 64 + fb + 2 * p];
                const float f1 = freqs[d * 64 + fb + 2 * p + 1];
                float c0, s0, c1, s1;
                __sincosf(x * f0 * 6.283185307179586477f, &s0, &c0);
                __sincosf(x * f1 * 6.283185307179586477f, &s1, &c1);
                pack_hilo(c0, c1, chi[p], clo[p]);
                pack_hilo(s0, s1, shi[p], slo[p]);
            }
            unsigned char* rowp = smem + SA + frow * RS;
            *reinterpret_cast<uint4*>(rowp + fb * 2)            = make_uint4(chi[0], chi[1], chi[2], chi[3]);
            *reinterpret_cast<uint4*>(rowp + fb * 2 + 16)       = make_uint4(chi[4], chi[5], chi[6], chi[7]);
            *reinterpret_cast<uint4*>(rowp + 128 + fb * 2)      = make_uint4(shi[0], shi[1], shi[2], shi[3]);
            *reinterpret_cast<uint4*>(rowp + 128 + fb * 2 + 16) = make_uint4(shi[4], shi[5], shi[6], shi[7]);
            *reinterpret_cast<uint4*>(rowp + 256 + fb * 2)      = make_uint4(clo[0], clo[1], clo[2], clo[3]);
            *reinterpret_cast<uint4*>(rowp + 256 + fb * 2 + 16) = make_uint4(clo[4], clo[5], clo[6], clo[7]);
            *reinterpret_cast<uint4*>(rowp + 384 + fb * 2)      = make_uint4(slo[0], slo[1], slo[2], slo[3]);
            *reinterpret_cast<uint4*>(rowp + 384 + fb * 2 + 16) = make_uint4(slo[4], slo[5], slo[6], slo[7]);
        }
        CP_WAIT0();
        __syncthreads();

        // ---- GEMM1 ----
        float acc[2][4][4];
#pragma unroll
        for (int i = 0; i < 2; ++i)
#pragma unroll
            for (int j = 0; j < 4; ++j)
#pragma unroll
                for (int q = 0; q < 4; ++q) acc[i][j][q] = 0.0f;
        gemm_bf16x3(aBase, bBase, acc);
        __syncthreads();  // all reads of s_A/s_B done

        // stage w2[d] image (overlaps epilogue)
        {
            const unsigned char* src = g_wimg + (4 + d) * IMG;
            for (int i = tid; i < IMG / 16; i += THREADS)
                cp_async16(sbase + SB + (uint32_t)i * 16u, src + i * 16);
            CP_COMMIT();
        }
        // ---- epi1: + x*w1_last + b1, LN, ReLU -> s_A (bf16 hi/lo) ----
        {
            const float* w1l = w1 + d * (129 * 128) + 128 * 128;
            const float* b1d = b1 + d * 128;
            float2 wl[4], bb[4];
#pragma unroll
            for (int nt = 0; nt < 4; ++nt) {
                const int c = nb + 8 * nt + 2 * m;
                wl[nt] = *reinterpret_cast<const float2*>(w1l + c);
                bb[nt] = *reinterpret_cast<const float2*>(b1d + c);
            }
            float v[4][4][2];
            float sum[4], sq[4];
#pragma unroll
            for (int j = 0; j < 4; ++j) {
                const float xr = cont[(row0 + rr[j]) * 4 + d];
                float s = 0.f, q = 0.f;
#pragma unroll
                for (int nt = 0; nt < 4; ++nt) {
                    const float v0 = acc[j >> 1][nt][2 * (j & 1)]     + xr * wl[nt].x + bb[nt].x;
                    const float v1 = acc[j >> 1][nt][2 * (j & 1) + 1] + xr * wl[nt].y + bb[nt].y;
                    v[j][nt][0] = v0; v[j][nt][1] = v1;
                    s += v0 + v1; q += v0 * v0 + v1 * v1;
                }
                sum[j] = s; sq[j] = q;
            }
#pragma unroll
            for (int msk = 1; msk <= 2; msk <<= 1)
#pragma unroll
                for (int j = 0; j < 4; ++j) {
                    sum[j] += __shfl_xor_sync(0xffffffffu, sum[j], msk);
                    sq[j]  += __shfl_xor_sync(0xffffffffu, sq[j],  msk);
                }
            if (m == 0)
#pragma unroll
                for (int j = 0; j < 4; ++j)
                    red[wx * 64 + rr[j]] = make_float2(sum[j], sq[j]);
            BAR_GRP(wy + 1);
#pragma unroll
            for (int j = 0; j < 4; ++j) {
#pragma unroll
                for (int ox = 0; ox < 4; ++ox)
                    if (ox != wx) {
                        const float2 o = red[ox * 64 + rr[j]];
                        sum[j] += o.x; sq[j] += o.y;
                    }
            }
            const float* gd = ln1g + d * 128;
            const float* bd = ln1b + d * 128;
#pragma unroll
            for (int j = 0; j < 4; ++j) {
                const float mu = sum[j] * (1.0f / 128.0f);
                const float rs = rsqrtf(sq[j] * (1.0f / 128.0f) - mu * mu + 1e-5f);
                unsigned char* rowp = smem + SA + rr[j] * RS;
#pragma unroll
                for (int nt = 0; nt < 4; ++nt) {
                    const int c = nb + 8 * nt + 2 * m;
                    const float2 gg = *reinterpret_cast<const float2*>(gd + c);
                    const float2 ee = *reinterpret_cast<const float2*>(bd + c);
                    const float h0 = fmaxf((v[j][nt][0] - mu) * rs * gg.x + ee.x, 0.f);
                    const float h1 = fmaxf((v[j][nt][1] - mu) * rs * gg.y + ee.y, 0.f);
                    uint32_t hi, lo;
                    pack_hilo(h0, h1, hi, lo);
                    *reinterpret_cast<uint32_t*>(rowp + c * 2)       = hi;
                    *reinterpret_cast<uint32_t*>(rowp + 256 + c * 2) = lo;
                }
            }
        }
        CP_WAIT0();
        __syncthreads();

        // ---- GEMM2 -> accE (accumulated over d) ----
        gemm_bf16x3(aBase, bBase, accE);
    }

    __syncthreads();
    // stage w3 image
    {
        const unsigned char* src = g_wimg + 8 * IMG;
        for (int i = tid; i < IMG / 16; i += THREADS)
            cp_async16(sbase + SB + (uint32_t)i * 16u, src + i * 16);
        CP_COMMIT();
    }
    // ---- epi2: + sum_d b2, LN(outg,outb), ReLU -> s_A ----
    {
        float v[4][4][2];
        float sum[4], sq[4];
        float2 bs[4];
#pragma unroll
        for (int nt = 0; nt < 4; ++nt) {
            const int c = nb + 8 * nt + 2 * m;
            bs[nt].x = b2[c] + b2[128 + c] + b2[256 + c] + b2[384 + c];
            bs[nt].y = b2[c + 1] + b2[128 + c + 1] + b2[256 + c + 1] + b2[384 + c + 1];
        }
#pragma unroll
        for (int j = 0; j < 4; ++j) {
            float s = 0.f, q = 0.f;
#pragma unroll
            for (int nt = 0; nt < 4; ++nt) {
                const float v0 = accE[j >> 1][nt][2 * (j & 1)]     + bs[nt].x;
                const float v1 = accE[j >> 1][nt][2 * (j & 1) + 1] + bs[nt].y;
                v[j][nt][0] = v0; v[j][nt][1] = v1;
                s += v0 + v1; q += v0 * v0 + v1 * v1;
            }
            sum[j] = s; sq[j] = q;
        }
#pragma unroll
        for (int msk = 1; msk <= 2; msk <<= 1)
#pragma unroll
            for (int j = 0; j < 4; ++j) {
                sum[j] += __shfl_xor_sync(0xffffffffu, sum[j], msk);
                sq[j]  += __shfl_xor_sync(0xffffffffu, sq[j],  msk);
            }
        if (m == 0)
#pragma unroll
            for (int j = 0; j < 4; ++j)
                red[wx * 64 + rr[j]] = make_float2(sum[j], sq[j]);
        BAR_GRP(wy + 1);
#pragma unroll
        for (int j = 0; j < 4; ++j) {
#pragma unroll
            for (int ox = 0; ox < 4; ++ox)
                if (ox != wx) {
                    const float2 o = red[ox * 64 + rr[j]];
                    sum[j] += o.x; sq[j] += o.y;
                }
        }
#pragma unroll
        for (int j = 0; j < 4; ++j) {
            const float mu = sum[j] * (1.0f / 128.0f);
            const float rs = rsqrtf(sq[j] * (1.0f / 128.0f) - mu * mu + 1e-5f);
            unsigned char* rowp = smem + SA + rr[j] * RS;
#pragma unroll
            for (int nt = 0; nt < 4; ++nt) {
                const int c = nb + 8 * nt + 2 * m;
                const float2 gg = *reinterpret_cast<const float2*>(outg + c);
                const float2 ee = *reinterpret_cast<const float2*>(outb + c);
                const float h0 = fmaxf((v[j][nt][0] - mu) * rs * gg.x + ee.x, 0.f);
                const float h1 = fmaxf((v[j][nt][1] - mu) * rs * gg.y + ee.y, 0.f);
                uint32_t hi, lo;
                pack_hilo(h0, h1, hi, lo);
                *reinterpret_cast<uint32_t*>(rowp + c * 2)       = hi;
                *reinterpret_cast<uint32_t*>(rowp + 256 + c * 2) = lo;
            }
        }
    }
    CP_WAIT0();
    __syncthreads();

    // ---- GEMM3 + b3 -> out ----
    float acc3[2][4][4];
#pragma unroll
    for (int i = 0; i < 2; ++i)
#pragma unroll
        for (int j = 0; j < 4; ++j)
#pragma unroll
            for (int q = 0; q < 4; ++q) acc3[i][j][q] = 0.0f;
    gemm_bf16x3(aBase, bBase, acc3);

#pragma unroll
    for (int j = 0; j < 4; ++j) {
        float* orow = out + (size_t)(row0 + rr[j]) * 128;
#pragma unroll
        for (int nt = 0; nt < 4; ++nt) {
            const int c = nb + 8 * nt + 2 * m;
            const float2 bb = *reinterpret_cast<const float2*>(b3 + c);
            *reinterpret_cast<float2*>(orow + c) =
                make_float2(acc3[j >> 1][nt][2 * (j & 1)]     + bb.x,
                            acc3[j >> 1][nt][2 * (j & 1) + 1] + bb.y);
        }
    }
}

// ---------------------------------------------------------------------------
extern "C" void kernel_launch(void* const* d_in, const int* in_sizes, int n_in,
                              void* d_out, int out_size)
{
    const float* cont  = (const float*)d_in[0];
    const float* freqs = (const float*)d_in[1];
    const float* w1    = (const float*)d_in[2];
    const float* b1    = (const float*)d_in[3];
    const float* ln1g  = (const float*)d_in[4];
    const float* ln1b  = (const float*)d_in[5];
    const float* w2    = (const float*)d_in[6];
    const float* b2    = (const float*)d_in[7];
    const float* outg  = (const float*)d_in[8];
    const float* outb  = (const float*)d_in[9];
    const float* w3    = (const float*)d_in[10];
    const float* b3    = (const float*)d_in[11];
    float* out = (float*)d_out;

    convert_weights_kernel<<<288, 256>>>(w1, w2, w3);

    cudaFuncSetAttribute(fe_mma_kernel,
                         cudaFuncAttributeMaxDynamicSharedMemorySize, SMEM_BYTES);
    fe_mma_kernel<<<NROWS / TM, THREADS, SMEM_BYTES>>>(
        cont, freqs, w1, b1, ln1g, ln1b, b2, outg, outb, b3, out);
}